// round 2
// baseline (speedup 1.0000x reference)
#include <cuda_runtime.h>
#include <cuda_bf16.h>
#include <cstdint>

// ---------------- problem constants ----------------
#define C_CLS   50000
#define NBLK    391                 // ceil(50000/128)
#define CPAD    (NBLK * 128)        // 50048
#define DK      512
#define BQ      512
#define S_SCALE 30.0f
#define SM_MARG 6.0f                // S * M
#define EPS_D2  1e-12f
#define NEG_INF (-1e30f)

// GEMM tiling
#define KC       64                 // K chunk per stage
#define ROWE     72                 // padded row length in bf16 elems (144 B)
#define MAT_E    (128 * ROWE)       // elems per matrix tile in smem
#define STAGE_E  (2 * MAT_E)        // A + B per stage
#define SMEM_BYTES (2 * STAGE_E * 2)  // 2 stages * elems * sizeof(bf16) = 73728

// ---------------- device scratch (no allocs allowed) ----------------
__device__ __align__(256) __nv_bfloat16 g_nmW[(size_t)CPAD * DK]; // zero-init: pad rows stay 0
__device__ __align__(256) __nv_bfloat16 g_A[1024 * DK];
__device__ float g_pmax[NBLK * BQ];
__device__ float g_psum[NBLK * BQ];
__device__ float g_tgt[BQ];
__device__ float g_interp[4 * NBLK];
__device__ float g_ce[BQ];

// ---------------- small helpers ----------------
static __device__ __forceinline__ uint32_t s32(const void* p) {
    return (uint32_t)__cvta_generic_to_shared(p);
}
static __device__ __forceinline__ void cp_async16(uint32_t dst, const void* src) {
    asm volatile("cp.async.cg.shared.global [%0], [%1], 16;" :: "r"(dst), "l"(src));
}
static __device__ __forceinline__ void cp_commit() {
    asm volatile("cp.async.commit_group;" ::: "memory");
}
template <int N>
static __device__ __forceinline__ void cp_wait() {
    asm volatile("cp.async.wait_group %0;" :: "n"(N) : "memory");
}
static __device__ __forceinline__ void ldm_x4(uint32_t& r0, uint32_t& r1, uint32_t& r2,
                                              uint32_t& r3, uint32_t addr) {
    asm volatile("ldmatrix.sync.aligned.m8n8.x4.shared.b16 {%0,%1,%2,%3}, [%4];"
                 : "=r"(r0), "=r"(r1), "=r"(r2), "=r"(r3) : "r"(addr));
}
static __device__ __forceinline__ void mma16816(float* d, const uint32_t* a, const uint32_t* b) {
    asm volatile(
        "mma.sync.aligned.m16n8k16.row.col.f32.bf16.bf16.f32 "
        "{%0,%1,%2,%3}, {%4,%5,%6,%7}, {%8,%9}, {%0,%1,%2,%3};"
        : "+f"(d[0]), "+f"(d[1]), "+f"(d[2]), "+f"(d[3])
        : "r"(a[0]), "r"(a[1]), "r"(a[2]), "r"(a[3]), "r"(b[0]), "r"(b[1]));
}

// ---------------- kernel 1: normalize W rows -> bf16 ----------------
__global__ void k_normalize(const float* __restrict__ W) {
    int c = blockIdx.x;                 // 0..C_CLS-1
    int t = threadIdx.x;                // 128 threads
    float4 v = ((const float4*)(W + (size_t)c * DK))[t];
    float ss = v.x * v.x + v.y * v.y + v.z * v.z + v.w * v.w;
    #pragma unroll
    for (int o = 16; o > 0; o >>= 1) ss += __shfl_xor_sync(0xFFFFFFFFu, ss, o);
    __shared__ float sred[4];
    if ((t & 31) == 0) sred[t >> 5] = ss;
    __syncthreads();
    float inv = rsqrtf(sred[0] + sred[1] + sred[2] + sred[3]);
    __nv_bfloat162 p0 = __floats2bfloat162_rn(v.x * inv, v.y * inv);
    __nv_bfloat162 p1 = __floats2bfloat162_rn(v.z * inv, v.w * inv);
    uint2 o;
    o.x = *(uint32_t*)&p0;
    o.y = *(uint32_t*)&p1;
    ((uint2*)(g_nmW + (size_t)c * DK))[t] = o;
}

// ---------------- kernel 2: build A = [bf16(emb); nm_W[y]] ----------------
__global__ void k_buildA(const float* __restrict__ emb, const int* __restrict__ y) {
    int r = blockIdx.x;                 // 0..1023
    int t = threadIdx.x;                // 128 threads
    if (r < BQ) {
        float4 v = ((const float4*)(emb + (size_t)r * DK))[t];
        __nv_bfloat162 p0 = __floats2bfloat162_rn(v.x, v.y);
        __nv_bfloat162 p1 = __floats2bfloat162_rn(v.z, v.w);
        uint2 o;
        o.x = *(uint32_t*)&p0;
        o.y = *(uint32_t*)&p1;
        ((uint2*)(g_A + (size_t)r * DK))[t] = o;
    } else {
        int cls = y[r - BQ];
        ((uint2*)(g_A + (size_t)r * DK))[t] = ((const uint2*)(g_nmW + (size_t)cls * DK))[t];
    }
}

// ---------------- kernel 3: fused GEMM + epilogue ----------------
extern __shared__ __nv_bfloat16 smem[];

static __device__ __forceinline__ void load_tile(int stage, int k0, int mb, int nb) {
    const __nv_bfloat16* Ag = g_A + (size_t)(mb * 128) * DK + k0;
    const __nv_bfloat16* Bg = g_nmW + (size_t)(nb * 128) * DK + k0;
    __nv_bfloat16* As = smem + stage * STAGE_E;
    __nv_bfloat16* Bs = As + MAT_E;
    int t = threadIdx.x;
    #pragma unroll
    for (int i = 0; i < 4; i++) {
        int idx = t + i * 256;          // 0..1023
        int row = idx >> 3;             // 0..127
        int cc  = idx & 7;              // 16B chunk
        cp_async16(s32(As + row * ROWE + cc * 8), Ag + (size_t)row * DK + cc * 8);
        cp_async16(s32(Bs + row * ROWE + cc * 8), Bg + (size_t)row * DK + cc * 8);
    }
}

__global__ __launch_bounds__(256, 2) void k_gemm(const int* __restrict__ y) {
    int nb = blockIdx.x;                // 0..NBLK-1
    int mb = blockIdx.y;                // 0..7
    int t = threadIdx.x;
    int lane = t & 31;
    int warp = t >> 5;
    int wm = warp >> 1;                 // 0..3 (M direction, 32 rows each)
    int wn = warp & 1;                  // 0..1 (N direction, 64 cols each)

    float acc[2][8][4];
    #pragma unroll
    for (int i = 0; i < 2; i++)
        #pragma unroll
        for (int j = 0; j < 8; j++)
            #pragma unroll
            for (int k = 0; k < 4; k++) acc[i][j][k] = 0.f;

    load_tile(0, 0, mb, nb);  cp_commit();
    load_tile(1, KC, mb, nb); cp_commit();

    #pragma unroll 1
    for (int kt = 0; kt < DK / KC; kt++) {
        cp_wait<1>();
        __syncthreads();
        const __nv_bfloat16* As = smem + (kt & 1) * STAGE_E;
        const __nv_bfloat16* Bs = As + MAT_E;
        uint32_t a_base = s32(As);
        uint32_t b_base = s32(Bs);
        #pragma unroll
        for (int ks = 0; ks < KC / 16; ks++) {
            int k0 = ks * 16;
            uint32_t a[2][4];
            #pragma unroll
            for (int tm = 0; tm < 2; tm++) {
                int row = wm * 32 + tm * 16 + (lane & 15);
                int col = k0 + (lane >> 4) * 8;
                ldm_x4(a[tm][0], a[tm][1], a[tm][2], a[tm][3],
                       a_base + (uint32_t)(row * ROWE + col) * 2);
            }
            uint32_t b[8][2];
            #pragma unroll
            for (int tp = 0; tp < 4; tp++) {
                int nrow = wn * 64 + tp * 16 + (lane & 7) + ((lane >> 4) << 3);
                int col = k0 + ((lane >> 3) & 1) * 8;
                uint32_t r0, r1, r2, r3;
                ldm_x4(r0, r1, r2, r3, b_base + (uint32_t)(nrow * ROWE + col) * 2);
                b[tp * 2][0] = r0;     b[tp * 2][1] = r1;
                b[tp * 2 + 1][0] = r2; b[tp * 2 + 1][1] = r3;
            }
            #pragma unroll
            for (int tm = 0; tm < 2; tm++)
                #pragma unroll
                for (int tn = 0; tn < 8; tn++)
                    mma16816(acc[tm][tn], a[tm], b[tn]);
        }
        __syncthreads();
        if (kt + 2 < DK / KC) {
            load_tile(kt & 1, (kt + 2) * KC, mb, nb);
            cp_commit();
        }
    }

    // -------- epilogue (smem reused as float scratch; last __syncthreads done) --------
    float* red = (float*)smem;          // 256 floats used

    if (mb < 4) {
        // CE rows: scale, margin, mask; per-row max + sum(exp)
        float rmax[2][2] = {{NEG_INF, NEG_INF}, {NEG_INF, NEG_INF}};
        #pragma unroll
        for (int tm = 0; tm < 2; tm++) {
            #pragma unroll
            for (int h = 0; h < 2; h++) {
                int gr = mb * 128 + wm * 32 + tm * 16 + h * 8 + (lane >> 2);
                int yy = y[gr];
                #pragma unroll
                for (int tn = 0; tn < 8; tn++) {
                    #pragma unroll
                    for (int e = 0; e < 2; e++) {
                        int gc = nb * 128 + wn * 64 + tn * 8 + (lane & 3) * 2 + e;
                        int ai = h * 2 + e;
                        float v = S_SCALE * acc[tm][tn][ai];
                        if (gc >= C_CLS) v = NEG_INF;
                        else if (gc == yy) { v -= SM_MARG; g_tgt[gr] = v; }
                        acc[tm][tn][ai] = v;
                        rmax[tm][h] = fmaxf(rmax[tm][h], v);
                    }
                }
            }
        }
        // reduce max over the 4 lanes sharing a row
        #pragma unroll
        for (int tm = 0; tm < 2; tm++)
            #pragma unroll
            for (int h = 0; h < 2; h++) {
                float m = rmax[tm][h];
                m = fmaxf(m, __shfl_xor_sync(0xFFFFFFFFu, m, 1));
                m = fmaxf(m, __shfl_xor_sync(0xFFFFFFFFu, m, 2));
                rmax[tm][h] = m;
            }
        // cross-warp (wn) max via smem
        if ((lane & 3) == 0) {
            #pragma unroll
            for (int tm = 0; tm < 2; tm++)
                #pragma unroll
                for (int h = 0; h < 2; h++) {
                    int lr = wm * 32 + tm * 16 + h * 8 + (lane >> 2);
                    red[wn * 128 + lr] = rmax[tm][h];
                }
        }
        __syncthreads();
        #pragma unroll
        for (int tm = 0; tm < 2; tm++)
            #pragma unroll
            for (int h = 0; h < 2; h++) {
                int lr = wm * 32 + tm * 16 + h * 8 + (lane >> 2);
                rmax[tm][h] = fmaxf(red[lr], red[128 + lr]);
            }
        __syncthreads();
        // sum(exp)
        float rsum[2][2] = {{0.f, 0.f}, {0.f, 0.f}};
        #pragma unroll
        for (int tm = 0; tm < 2; tm++)
            #pragma unroll
            for (int h = 0; h < 2; h++)
                #pragma unroll
                for (int tn = 0; tn < 8; tn++)
                    #pragma unroll
                    for (int e = 0; e < 2; e++)
                        rsum[tm][h] += __expf(acc[tm][tn][h * 2 + e] - rmax[tm][h]);
        #pragma unroll
        for (int tm = 0; tm < 2; tm++)
            #pragma unroll
            for (int h = 0; h < 2; h++) {
                float s = rsum[tm][h];
                s += __shfl_xor_sync(0xFFFFFFFFu, s, 1);
                s += __shfl_xor_sync(0xFFFFFFFFu, s, 2);
                rsum[tm][h] = s;
            }
        if ((lane & 3) == 0) {
            #pragma unroll
            for (int tm = 0; tm < 2; tm++)
                #pragma unroll
                for (int h = 0; h < 2; h++) {
                    int lr = wm * 32 + tm * 16 + h * 8 + (lane >> 2);
                    red[wn * 128 + lr] = rsum[tm][h];
                }
        }
        __syncthreads();
        if (wn == 0 && (lane & 3) == 0) {
            #pragma unroll
            for (int tm = 0; tm < 2; tm++)
                #pragma unroll
                for (int h = 0; h < 2; h++) {
                    int lr = wm * 32 + tm * 16 + h * 8 + (lane >> 2);
                    int gr = mb * 128 + lr;
                    g_pmax[nb * BQ + gr] = rmax[tm][h];
                    g_psum[nb * BQ + gr] = red[lr] + red[128 + lr];
                }
        }
    } else {
        // MHE rows: sum over valid (col<C, col != y) of 1 / max(2 - 2g, eps)
        float part = 0.f;
        #pragma unroll
        for (int tm = 0; tm < 2; tm++) {
            #pragma unroll
            for (int h = 0; h < 2; h++) {
                int gr = mb * 128 + wm * 32 + tm * 16 + h * 8 + (lane >> 2);
                int yy = y[gr - BQ];
                #pragma unroll
                for (int tn = 0; tn < 8; tn++) {
                    #pragma unroll
                    for (int e = 0; e < 2; e++) {
                        int gc = nb * 128 + wn * 64 + tn * 8 + (lane & 3) * 2 + e;
                        if (gc < C_CLS && gc != yy) {
                            float g = acc[tm][tn][h * 2 + e];
                            float d2 = fmaxf(2.f - 2.f * g, EPS_D2);
                            part += 1.f / d2;
                        }
                    }
                }
            }
        }
        #pragma unroll
        for (int o = 16; o > 0; o >>= 1) part += __shfl_xor_sync(0xFFFFFFFFu, part, o);
        if (lane == 0) red[warp] = part;
        __syncthreads();
        if (t == 0) {
            float s = 0.f;
            #pragma unroll
            for (int w = 0; w < 8; w++) s += red[w];
            g_interp[(mb - 4) * NBLK + nb] = s;
        }
    }
}

// ---------------- kernel 4: per-row logsumexp -> CE ----------------
__global__ void k_ce() {
    int r = blockIdx.x * 128 + threadIdx.x;    // grid 4 x 128
    float m = NEG_INF, s = 0.f;
    for (int nt = 0; nt < NBLK; nt++) {
        float pm = g_pmax[nt * BQ + r];
        float ps = g_psum[nt * BQ + r];
        if (pm > m) {
            s = s * __expf(m - pm) + ps;
            m = pm;
        } else {
            s += ps * __expf(pm - m);
        }
    }
    g_ce[r] = m + logf(s) - g_tgt[r];
}

// ---------------- kernel 5: final scalar ----------------
__global__ void k_final(float* __restrict__ out) {
    int t = threadIdx.x;                       // 256
    int lane = t & 31, warp = t >> 5;
    float sce = 0.f, sin_ = 0.f;
    for (int i = t; i < BQ; i += 256) sce += g_ce[i];
    for (int i = t; i < 4 * NBLK; i += 256) sin_ += g_interp[i];
    #pragma unroll
    for (int o = 16; o > 0; o >>= 1) {
        sce += __shfl_xor_sync(0xFFFFFFFFu, sce, o);
        sin_ += __shfl_xor_sync(0xFFFFFFFFu, sin_, o);
    }
    __shared__ float r1[8], r2[8];
    if (lane == 0) { r1[warp] = sce; r2[warp] = sin_; }
    __syncthreads();
    if (t == 0) {
        float a = 0.f, b = 0.f;
        #pragma unroll
        for (int w = 0; w < 8; w++) { a += r1[w]; b += r2[w]; }
        out[0] = a / (float)BQ + b / ((float)BQ * (float)(C_CLS - 1));
    }
}

// ---------------- launcher ----------------
extern "C" void kernel_launch(void* const* d_in, const int* in_sizes, int n_in,
                              void* d_out, int out_size) {
    const float* emb = (const float*)d_in[0];
    const float* W   = (const float*)d_in[1];
    const int*   y   = (const int*)d_in[2];
    float* out = (float*)d_out;

    k_normalize<<<C_CLS, 128>>>(W);
    k_buildA<<<1024, 128>>>(emb, y);

    cudaFuncSetAttribute(k_gemm, cudaFuncAttributeMaxDynamicSharedMemorySize, SMEM_BYTES);
    dim3 grid(NBLK, 8);
    k_gemm<<<grid, 256, SMEM_BYTES>>>(y);

    k_ce<<<4, 128>>>();
    k_final<<<1, 256>>>(out);
}

// round 3
// speedup vs baseline: 1.2857x; 1.2857x over previous
#include <cuda_runtime.h>
#include <cuda_bf16.h>
#include <cstdint>

// ---------------- problem constants ----------------
#define C_CLS   50000
#define NBLK    391                 // ceil(50000/128)
#define CPAD    (NBLK * 128)        // 50048
#define DK      512
#define BQ      512
#define S_SCALE 30.0f
#define SM_MARG 6.0f                // S * M
#define EPS_D2  1e-12f
#define NEG_INF (-1e30f)

// GEMM tiling
#define KC       64                 // K chunk per stage
#define ROWE     72                 // padded row length in bf16 elems (144 B)
#define MAT_E    (128 * ROWE)       // elems per matrix tile in smem
#define STAGE_E  (2 * MAT_E)        // A + B per stage
#define SMEM_BYTES (2 * STAGE_E * 2)  // 2 stages * elems * sizeof(bf16) = 73728

// ---------------- device scratch (no allocs allowed) ----------------
__device__ __align__(256) __nv_bfloat16 g_nmW[(size_t)CPAD * DK]; // zero-init: pad rows stay 0
__device__ __align__(256) __nv_bfloat16 g_A[1024 * DK];
__device__ float g_pmax[BQ * NBLK];   // [row][nblk] — contiguous per row
__device__ float g_psum[BQ * NBLK];
__device__ float g_tgt[BQ];
__device__ float g_interp[4 * NBLK];
__device__ float g_ce[BQ];

// ---------------- small helpers ----------------
static __device__ __forceinline__ uint32_t s32(const void* p) {
    return (uint32_t)__cvta_generic_to_shared(p);
}
static __device__ __forceinline__ void cp_async16(uint32_t dst, const void* src) {
    asm volatile("cp.async.cg.shared.global [%0], [%1], 16;" :: "r"(dst), "l"(src));
}
static __device__ __forceinline__ void cp_commit() {
    asm volatile("cp.async.commit_group;" ::: "memory");
}
template <int N>
static __device__ __forceinline__ void cp_wait() {
    asm volatile("cp.async.wait_group %0;" :: "n"(N) : "memory");
}
static __device__ __forceinline__ void ldm_x4(uint32_t& r0, uint32_t& r1, uint32_t& r2,
                                              uint32_t& r3, uint32_t addr) {
    asm volatile("ldmatrix.sync.aligned.m8n8.x4.shared.b16 {%0,%1,%2,%3}, [%4];"
                 : "=r"(r0), "=r"(r1), "=r"(r2), "=r"(r3) : "r"(addr));
}
static __device__ __forceinline__ void mma16816(float* d, const uint32_t* a, const uint32_t* b) {
    asm volatile(
        "mma.sync.aligned.m16n8k16.row.col.f32.bf16.bf16.f32 "
        "{%0,%1,%2,%3}, {%4,%5,%6,%7}, {%8,%9}, {%0,%1,%2,%3};"
        : "+f"(d[0]), "+f"(d[1]), "+f"(d[2]), "+f"(d[3])
        : "r"(a[0]), "r"(a[1]), "r"(a[2]), "r"(a[3]), "r"(b[0]), "r"(b[1]));
}

// ---------------- kernel 1: normalize W rows -> bf16 ----------------
__global__ void k_normalize(const float* __restrict__ W) {
    int c = blockIdx.x;                 // 0..C_CLS-1
    int t = threadIdx.x;                // 128 threads
    float4 v = ((const float4*)(W + (size_t)c * DK))[t];
    float ss = v.x * v.x + v.y * v.y + v.z * v.z + v.w * v.w;
    #pragma unroll
    for (int o = 16; o > 0; o >>= 1) ss += __shfl_xor_sync(0xFFFFFFFFu, ss, o);
    __shared__ float sred[4];
    if ((t & 31) == 0) sred[t >> 5] = ss;
    __syncthreads();
    float inv = rsqrtf(sred[0] + sred[1] + sred[2] + sred[3]);
    __nv_bfloat162 p0 = __floats2bfloat162_rn(v.x * inv, v.y * inv);
    __nv_bfloat162 p1 = __floats2bfloat162_rn(v.z * inv, v.w * inv);
    uint2 o;
    o.x = *(uint32_t*)&p0;
    o.y = *(uint32_t*)&p1;
    ((uint2*)(g_nmW + (size_t)c * DK))[t] = o;
}

// ---------------- kernel 2: build A = [bf16(emb); nm_W[y]] ----------------
__global__ void k_buildA(const float* __restrict__ emb, const int* __restrict__ y) {
    int r = blockIdx.x;                 // 0..1023
    int t = threadIdx.x;                // 128 threads
    if (r < BQ) {
        float4 v = ((const float4*)(emb + (size_t)r * DK))[t];
        __nv_bfloat162 p0 = __floats2bfloat162_rn(v.x, v.y);
        __nv_bfloat162 p1 = __floats2bfloat162_rn(v.z, v.w);
        uint2 o;
        o.x = *(uint32_t*)&p0;
        o.y = *(uint32_t*)&p1;
        ((uint2*)(g_A + (size_t)r * DK))[t] = o;
    } else {
        int cls = y[r - BQ];
        ((uint2*)(g_A + (size_t)r * DK))[t] = ((const uint2*)(g_nmW + (size_t)cls * DK))[t];
    }
}

// ---------------- kernel 3: fused GEMM + epilogue ----------------
extern __shared__ __nv_bfloat16 smem[];

static __device__ __forceinline__ void load_tile(int stage, int k0, int mb, int nb) {
    const __nv_bfloat16* Ag = g_A + (size_t)(mb * 128) * DK + k0;
    const __nv_bfloat16* Bg = g_nmW + (size_t)(nb * 128) * DK + k0;
    __nv_bfloat16* As = smem + stage * STAGE_E;
    __nv_bfloat16* Bs = As + MAT_E;
    int t = threadIdx.x;
    #pragma unroll
    for (int i = 0; i < 4; i++) {
        int idx = t + i * 256;          // 0..1023
        int row = idx >> 3;             // 0..127
        int cc  = idx & 7;              // 16B chunk
        cp_async16(s32(As + row * ROWE + cc * 8), Ag + (size_t)row * DK + cc * 8);
        cp_async16(s32(Bs + row * ROWE + cc * 8), Bg + (size_t)row * DK + cc * 8);
    }
}

__global__ __launch_bounds__(256, 2) void k_gemm(const int* __restrict__ y) {
    int nb = blockIdx.x;                // 0..NBLK-1
    int mb = blockIdx.y;                // 0..7
    int t = threadIdx.x;
    int lane = t & 31;
    int warp = t >> 5;
    int wm = warp >> 1;                 // 0..3 (M direction, 32 rows each)
    int wn = warp & 1;                  // 0..1 (N direction, 64 cols each)

    float acc[2][8][4];
    #pragma unroll
    for (int i = 0; i < 2; i++)
        #pragma unroll
        for (int j = 0; j < 8; j++)
            #pragma unroll
            for (int k = 0; k < 4; k++) acc[i][j][k] = 0.f;

    load_tile(0, 0, mb, nb);  cp_commit();
    load_tile(1, KC, mb, nb); cp_commit();

    #pragma unroll 1
    for (int kt = 0; kt < DK / KC; kt++) {
        cp_wait<1>();
        __syncthreads();
        const __nv_bfloat16* As = smem + (kt & 1) * STAGE_E;
        const __nv_bfloat16* Bs = As + MAT_E;
        uint32_t a_base = s32(As);
        uint32_t b_base = s32(Bs);
        #pragma unroll
        for (int ks = 0; ks < KC / 16; ks++) {
            int k0 = ks * 16;
            uint32_t a[2][4];
            #pragma unroll
            for (int tm = 0; tm < 2; tm++) {
                int row = wm * 32 + tm * 16 + (lane & 15);
                int col = k0 + (lane >> 4) * 8;
                ldm_x4(a[tm][0], a[tm][1], a[tm][2], a[tm][3],
                       a_base + (uint32_t)(row * ROWE + col) * 2);
            }
            uint32_t b[8][2];
            #pragma unroll
            for (int tp = 0; tp < 4; tp++) {
                int nrow = wn * 64 + tp * 16 + (lane & 7) + ((lane >> 4) << 3);
                int col = k0 + ((lane >> 3) & 1) * 8;
                uint32_t r0, r1, r2, r3;
                ldm_x4(r0, r1, r2, r3, b_base + (uint32_t)(nrow * ROWE + col) * 2);
                b[tp * 2][0] = r0;     b[tp * 2][1] = r1;
                b[tp * 2 + 1][0] = r2; b[tp * 2 + 1][1] = r3;
            }
            #pragma unroll
            for (int tm = 0; tm < 2; tm++)
                #pragma unroll
                for (int tn = 0; tn < 8; tn++)
                    mma16816(acc[tm][tn], a[tm], b[tn]);
        }
        __syncthreads();
        if (kt + 2 < DK / KC) {
            load_tile(kt & 1, (kt + 2) * KC, mb, nb);
            cp_commit();
        }
    }

    // -------- epilogue (smem reused as float scratch; last __syncthreads done) --------
    float* red = (float*)smem;          // 256 floats used

    if (mb < 4) {
        // CE rows: scale, margin, mask; per-row max + sum(exp)
        float rmax[2][2] = {{NEG_INF, NEG_INF}, {NEG_INF, NEG_INF}};
        #pragma unroll
        for (int tm = 0; tm < 2; tm++) {
            #pragma unroll
            for (int h = 0; h < 2; h++) {
                int gr = mb * 128 + wm * 32 + tm * 16 + h * 8 + (lane >> 2);
                int yy = y[gr];
                #pragma unroll
                for (int tn = 0; tn < 8; tn++) {
                    #pragma unroll
                    for (int e = 0; e < 2; e++) {
                        int gc = nb * 128 + wn * 64 + tn * 8 + (lane & 3) * 2 + e;
                        int ai = h * 2 + e;
                        float v = S_SCALE * acc[tm][tn][ai];
                        if (gc >= C_CLS) v = NEG_INF;
                        else if (gc == yy) { v -= SM_MARG; g_tgt[gr] = v; }
                        acc[tm][tn][ai] = v;
                        rmax[tm][h] = fmaxf(rmax[tm][h], v);
                    }
                }
            }
        }
        // reduce max over the 4 lanes sharing a row
        #pragma unroll
        for (int tm = 0; tm < 2; tm++)
            #pragma unroll
            for (int h = 0; h < 2; h++) {
                float m = rmax[tm][h];
                m = fmaxf(m, __shfl_xor_sync(0xFFFFFFFFu, m, 1));
                m = fmaxf(m, __shfl_xor_sync(0xFFFFFFFFu, m, 2));
                rmax[tm][h] = m;
            }
        // cross-warp (wn) max via smem
        if ((lane & 3) == 0) {
            #pragma unroll
            for (int tm = 0; tm < 2; tm++)
                #pragma unroll
                for (int h = 0; h < 2; h++) {
                    int lr = wm * 32 + tm * 16 + h * 8 + (lane >> 2);
                    red[wn * 128 + lr] = rmax[tm][h];
                }
        }
        __syncthreads();
        #pragma unroll
        for (int tm = 0; tm < 2; tm++)
            #pragma unroll
            for (int h = 0; h < 2; h++) {
                int lr = wm * 32 + tm * 16 + h * 8 + (lane >> 2);
                rmax[tm][h] = fmaxf(red[lr], red[128 + lr]);
            }
        __syncthreads();
        // sum(exp)
        float rsum[2][2] = {{0.f, 0.f}, {0.f, 0.f}};
        #pragma unroll
        for (int tm = 0; tm < 2; tm++)
            #pragma unroll
            for (int h = 0; h < 2; h++)
                #pragma unroll
                for (int tn = 0; tn < 8; tn++)
                    #pragma unroll
                    for (int e = 0; e < 2; e++)
                        rsum[tm][h] += __expf(acc[tm][tn][h * 2 + e] - rmax[tm][h]);
        #pragma unroll
        for (int tm = 0; tm < 2; tm++)
            #pragma unroll
            for (int h = 0; h < 2; h++) {
                float s = rsum[tm][h];
                s += __shfl_xor_sync(0xFFFFFFFFu, s, 1);
                s += __shfl_xor_sync(0xFFFFFFFFu, s, 2);
                rsum[tm][h] = s;
            }
        if ((lane & 3) == 0) {
            #pragma unroll
            for (int tm = 0; tm < 2; tm++)
                #pragma unroll
                for (int h = 0; h < 2; h++) {
                    int lr = wm * 32 + tm * 16 + h * 8 + (lane >> 2);
                    red[wn * 128 + lr] = rsum[tm][h];
                }
        }
        __syncthreads();
        if (wn == 0 && (lane & 3) == 0) {
            #pragma unroll
            for (int tm = 0; tm < 2; tm++)
                #pragma unroll
                for (int h = 0; h < 2; h++) {
                    int lr = wm * 32 + tm * 16 + h * 8 + (lane >> 2);
                    int gr = mb * 128 + lr;
                    g_pmax[(size_t)gr * NBLK + nb] = rmax[tm][h];
                    g_psum[(size_t)gr * NBLK + nb] = red[lr] + red[128 + lr];
                }
        }
    } else {
        // MHE rows: sum over valid (col<C, col != y) of 1 / max(2 - 2g, eps)
        float part = 0.f;
        #pragma unroll
        for (int tm = 0; tm < 2; tm++) {
            #pragma unroll
            for (int h = 0; h < 2; h++) {
                int gr = mb * 128 + wm * 32 + tm * 16 + h * 8 + (lane >> 2);
                int yy = y[gr - BQ];
                #pragma unroll
                for (int tn = 0; tn < 8; tn++) {
                    #pragma unroll
                    for (int e = 0; e < 2; e++) {
                        int gc = nb * 128 + wn * 64 + tn * 8 + (lane & 3) * 2 + e;
                        if (gc < C_CLS && gc != yy) {
                            float g = acc[tm][tn][h * 2 + e];
                            float d2 = fmaxf(2.f - 2.f * g, EPS_D2);
                            part += 1.f / d2;
                        }
                    }
                }
            }
        }
        #pragma unroll
        for (int o = 16; o > 0; o >>= 1) part += __shfl_xor_sync(0xFFFFFFFFu, part, o);
        if (lane == 0) red[warp] = part;
        __syncthreads();
        if (t == 0) {
            float s = 0.f;
            #pragma unroll
            for (int w = 0; w < 8; w++) s += red[w];
            g_interp[(mb - 4) * NBLK + nb] = s;
        }
    }
}

// ---------------- kernel 4: per-row logsumexp -> CE (parallel) ----------------
__global__ void k_ce() {
    int r = blockIdx.x;                        // 0..511 (one block per row)
    int t = threadIdx.x;                       // 128 threads
    const float* pm = g_pmax + (size_t)r * NBLK;
    const float* ps = g_psum + (size_t)r * NBLK;
    float m = NEG_INF, s = 0.f;
    for (int i = t; i < NBLK; i += 128) {
        float a = pm[i], b = ps[i];
        if (a > m) { s = s * __expf(m - a) + b; m = a; }
        else       { s += b * __expf(a - m); }
    }
    // warp-level (m,s) combine
    #pragma unroll
    for (int o = 16; o > 0; o >>= 1) {
        float mo = __shfl_xor_sync(0xFFFFFFFFu, m, o);
        float so = __shfl_xor_sync(0xFFFFFFFFu, s, o);
        float nm = fmaxf(m, mo);
        s = s * __expf(m - nm) + so * __expf(mo - nm);
        m = nm;
    }
    __shared__ float sm[4], ss[4];
    if ((t & 31) == 0) { sm[t >> 5] = m; ss[t >> 5] = s; }
    __syncthreads();
    if (t == 0) {
        float M = sm[0], S = ss[0];
        #pragma unroll
        for (int w = 1; w < 4; w++) {
            float nm = fmaxf(M, sm[w]);
            S = S * __expf(M - nm) + ss[w] * __expf(sm[w] - nm);
            M = nm;
        }
        g_ce[r] = M + logf(S) - g_tgt[r];
    }
}

// ---------------- kernel 5: final scalar ----------------
__global__ void k_final(float* __restrict__ out) {
    int t = threadIdx.x;                       // 256
    int lane = t & 31, warp = t >> 5;
    float sce = 0.f, sin_ = 0.f;
    for (int i = t; i < BQ; i += 256) sce += g_ce[i];
    for (int i = t; i < 4 * NBLK; i += 256) sin_ += g_interp[i];
    #pragma unroll
    for (int o = 16; o > 0; o >>= 1) {
        sce += __shfl_xor_sync(0xFFFFFFFFu, sce, o);
        sin_ += __shfl_xor_sync(0xFFFFFFFFu, sin_, o);
    }
    __shared__ float r1[8], r2[8];
    if (lane == 0) { r1[warp] = sce; r2[warp] = sin_; }
    __syncthreads();
    if (t == 0) {
        float a = 0.f, b = 0.f;
        #pragma unroll
        for (int w = 0; w < 8; w++) { a += r1[w]; b += r2[w]; }
        out[0] = a / (float)BQ + b / ((float)BQ * (float)(C_CLS - 1));
    }
}

// ---------------- launcher ----------------
extern "C" void kernel_launch(void* const* d_in, const int* in_sizes, int n_in,
                              void* d_out, int out_size) {
    const float* emb = (const float*)d_in[0];
    const float* W   = (const float*)d_in[1];
    const int*   y   = (const int*)d_in[2];
    float* out = (float*)d_out;

    k_normalize<<<C_CLS, 128>>>(W);
    k_buildA<<<1024, 128>>>(emb, y);

    cudaFuncSetAttribute(k_gemm, cudaFuncAttributeMaxDynamicSharedMemorySize, SMEM_BYTES);
    dim3 grid(NBLK, 8);
    k_gemm<<<grid, 256, SMEM_BYTES>>>(y);

    k_ce<<<BQ, 128>>>();
    k_final<<<1, 256>>>(out);
}